// round 16
// baseline (speedup 1.0000x reference)
#include <cuda_runtime.h>
#include <cuda_bf16.h>
#include <math.h>

#define NMAX 100000
#define EMAX 1700000
#define HID 128
#define PROTO 64
#define BN_EPS 1e-5f
#define KC 32

typedef unsigned int uint32;

// ---------------- scratch (device globals: no allocation allowed) ----------------
__device__ float g_h1[NMAX * HID];
__device__ float g_h2[NMAX * HID];
__device__ float g_agg[NMAX * HID];
__device__ float g_p[NMAX * HID];
__device__ float g_p2[NMAX * HID];
__device__ float g_an[NMAX * PROTO];
__device__ int   g_cnt[NMAX];
__device__ int   g_off[NMAX + 1];
__device__ int   g_cur[NMAX];
__device__ int   g_csr[EMAX];
__device__ int   g_total;
__device__ float g_sum[4 * HID];
__device__ float g_sumsq[4 * HID];
__device__ float g_scaleS[4][HID];
__device__ float g_shiftS[4][HID];

// Weights in INTERLEAVED tf32 fragment layout: one float4 per "pair"
#define WPL(L) ((L) * 8192)
#define WPR(L) (24576 + (L) * 8192)
#define MP0 49152
#define MP1 53248
#define MP2 61440
#define NPAIRS 69632
__device__ float g_wf[NPAIRS * 4];

// ---------------- tf32 + cache-hint helpers ----------------
__device__ __forceinline__ uint32 cvt_tf32(float x) {
    uint32 r;
    asm("cvt.rna.tf32.f32 %0, %1;" : "=r"(r) : "f"(x));
    return r;
}
__device__ __forceinline__ void split_tf32(float x, float& hi, float& lo) {
    uint32 h = cvt_tf32(x);
    hi = __uint_as_float(h);
    lo = __uint_as_float(cvt_tf32(x - hi));
}
__device__ __forceinline__ void mma_tf32(float* c,
                                         uint32 a0, uint32 a1, uint32 a2, uint32 a3,
                                         uint32 b0, uint32 b1) {
    asm volatile("mma.sync.aligned.m16n8k8.row.col.f32.tf32.tf32.f32 "
                 "{%0,%1,%2,%3}, {%4,%5,%6,%7}, {%8,%9}, {%0,%1,%2,%3};"
                 : "+f"(c[0]), "+f"(c[1]), "+f"(c[2]), "+f"(c[3])
                 : "r"(a0), "r"(a1), "r"(a2), "r"(a3), "r"(b0), "r"(b1));
}
__device__ __forceinline__ float4 ldg_ef4(const float* p) {
    float4 v;
    asm("ld.global.nc.L1::evict_first.v4.f32 {%0,%1,%2,%3}, [%4];"
        : "=f"(v.x), "=f"(v.y), "=f"(v.z), "=f"(v.w) : "l"(p));
    return v;
}
__device__ __forceinline__ float4 ldg_el4(const float* p) {
    float4 v;
    asm("ld.global.nc.L1::evict_last.v4.f32 {%0,%1,%2,%3}, [%4];"
        : "=f"(v.x), "=f"(v.y), "=f"(v.z), "=f"(v.w) : "l"(p));
    return v;
}

// ---------------- init ----------------
__global__ void init_kernel() {
    int v = blockIdx.x * blockDim.x + threadIdx.x;
    if (v < 4 * HID) { g_sum[v] = 0.f; g_sumsq[v] = 0.f; }
    if (v == 0) g_total = 0;
}

__global__ void zero_cnt_kernel(int n) {
    int v = blockIdx.x * blockDim.x + threadIdx.x;
    if (v < n) g_cnt[v] = 0;
}
__global__ void count_kernel(const int* __restrict__ tgt, int E) {
    int e = blockIdx.x * blockDim.x + threadIdx.x;
    if (e < E) atomicAdd(&g_cnt[tgt[e]], 1);
}

// ---------------- CSR offset allocation (unordered block bases) ----------------
__global__ void alloc_kernel(int n) {
    __shared__ int wsums[8];
    __shared__ int base_s;
    int tid = threadIdx.x, lane = tid & 31, wid = tid >> 5;
    int i = blockIdx.x * 256 + tid;
    int v = (i < n) ? g_cnt[i] : 0;
    int s = v;
#pragma unroll
    for (int d = 1; d < 32; d <<= 1) {
        int t = __shfl_up_sync(0xFFFFFFFFu, s, d);
        if (lane >= d) s += t;
    }
    if (lane == 31) wsums[wid] = s;
    __syncthreads();
    if (tid == 0) {
        int run = 0;
#pragma unroll
        for (int w8 = 0; w8 < 8; w8++) { int t = wsums[w8]; wsums[w8] = run; run += t; }
        base_s = atomicAdd(&g_total, run);
    }
    __syncthreads();
    int excl = base_s + wsums[wid] + s - v;
    if (i < n) { g_off[i] = excl; g_cur[i] = excl; }
}

__global__ void fill_kernel(const int* __restrict__ src, const int* __restrict__ tgt, int E) {
    int e = blockIdx.x * blockDim.x + threadIdx.x;
    if (e >= E) return;
    int t = tgt[e];
    int pos = atomicAdd(&g_cur[t], 1);
    g_csr[pos] = src[e];
}

// ---------------- weight prep ----------------
__global__ void prep_w_kernel(const float* __restrict__ sWl, const float* __restrict__ sWr,
                              const float* __restrict__ m0, const float* __restrict__ m1,
                              const float* __restrict__ m2) {
    int i = blockIdx.x * blockDim.x + threadIdx.x;
    if (i >= NPAIRS) return;
    int off, K;
    const float* mat;
    if (i < 24576)        { int L = i / 8192;           off = L * 8192;           mat = sWl + L * 16384; K = 128; }
    else if (i < 49152)   { int L = (i - 24576) / 8192; off = 24576 + L * 8192;   mat = sWr + L * 16384; K = 128; }
    else if (i < 53248)   { off = MP0; mat = m0; K = 64; }
    else if (i < 61440)   { off = MP1; mat = m1; K = 128; }
    else                  { off = MP2; mat = m2; K = 128; }
    int li   = i - off;
    int lane = li & 31;
    int nt   = (li >> 5) & 15;
    int kt   = li >> 9;
    int g4 = lane >> 2, t4 = lane & 3;
    int c = nt * 8 + g4;
    int k = kt * 8 + t4;
    float v0 = mat[c * K + k];
    float v1 = mat[c * K + k + 4];
    float h0, l0, h1, l1;
    split_tf32(v0, h0, l0);
    split_tf32(v1, h1, l1);
    *(float4*)&g_wf[(size_t)i * 4] = make_float4(h0, h1, l0, l1);
}

// ---------------- gather aggregation (segment mean), warp per node, MLP=4 ----------------
template<int SLOT>
__global__ __launch_bounds__(256) void gather_agg_kernel(const float* __restrict__ h,
                                                         float* __restrict__ agg, int n) {
    int lane = threadIdx.x & 31;
    int v = blockIdx.x * 8 + (threadIdx.x >> 5);
    if (v >= n) return;
    int d0 = g_off[v];
    int c = g_cnt[v];
    int d1 = d0 + c;
    float4 sc, sh;
    if (SLOT >= 0) {
        sc = *(const float4*)&g_scaleS[SLOT][lane * 4];
        sh = *(const float4*)&g_shiftS[SLOT][lane * 4];
    }
    float4 acc = make_float4(0.f, 0.f, 0.f, 0.f);
    for (int j0 = d0; j0 < d1; j0 += 32) {
        int m = d1 - j0; if (m > 32) m = 32;
        int ul = (j0 + lane < d1) ? g_csr[j0 + lane] : 0;
        int t = 0;
        for (; t + 4 <= m; t += 4) {
            int u0 = __shfl_sync(0xFFFFFFFFu, ul, t);
            int u1 = __shfl_sync(0xFFFFFFFFu, ul, t + 1);
            int u2 = __shfl_sync(0xFFFFFFFFu, ul, t + 2);
            int u3 = __shfl_sync(0xFFFFFFFFu, ul, t + 3);
            float4 x0 = *(const float4*)(h + (size_t)u0 * HID + lane * 4);
            float4 x1 = *(const float4*)(h + (size_t)u1 * HID + lane * 4);
            float4 x2 = *(const float4*)(h + (size_t)u2 * HID + lane * 4);
            float4 x3 = *(const float4*)(h + (size_t)u3 * HID + lane * 4);
            if (SLOT >= 0) {
                x0.x = fmaxf(x0.x * sc.x + sh.x, 0.f); x0.y = fmaxf(x0.y * sc.y + sh.y, 0.f);
                x0.z = fmaxf(x0.z * sc.z + sh.z, 0.f); x0.w = fmaxf(x0.w * sc.w + sh.w, 0.f);
                x1.x = fmaxf(x1.x * sc.x + sh.x, 0.f); x1.y = fmaxf(x1.y * sc.y + sh.y, 0.f);
                x1.z = fmaxf(x1.z * sc.z + sh.z, 0.f); x1.w = fmaxf(x1.w * sc.w + sh.w, 0.f);
                x2.x = fmaxf(x2.x * sc.x + sh.x, 0.f); x2.y = fmaxf(x2.y * sc.y + sh.y, 0.f);
                x2.z = fmaxf(x2.z * sc.z + sh.z, 0.f); x2.w = fmaxf(x2.w * sc.w + sh.w, 0.f);
                x3.x = fmaxf(x3.x * sc.x + sh.x, 0.f); x3.y = fmaxf(x3.y * sc.y + sh.y, 0.f);
                x3.z = fmaxf(x3.z * sc.z + sh.z, 0.f); x3.w = fmaxf(x3.w * sc.w + sh.w, 0.f);
            }
            acc.x += (x0.x + x1.x) + (x2.x + x3.x);
            acc.y += (x0.y + x1.y) + (x2.y + x3.y);
            acc.z += (x0.z + x1.z) + (x2.z + x3.z);
            acc.w += (x0.w + x1.w) + (x2.w + x3.w);
        }
        for (; t < m; t++) {
            int u = __shfl_sync(0xFFFFFFFFu, ul, t);
            float4 x = *(const float4*)(h + (size_t)u * HID + lane * 4);
            if (SLOT >= 0) {
                x.x = fmaxf(x.x * sc.x + sh.x, 0.f);
                x.y = fmaxf(x.y * sc.y + sh.y, 0.f);
                x.z = fmaxf(x.z * sc.z + sh.z, 0.f);
                x.w = fmaxf(x.w * sc.w + sh.w, 0.f);
            }
            acc.x += x.x; acc.y += x.y; acc.z += x.z; acc.w += x.w;
        }
    }
    float inv = 1.0f / (float)(c > 0 ? c : 1);
    acc.x *= inv; acc.y *= inv; acc.z *= inv; acc.w *= inv;
    *(float4*)(agg + (size_t)v * HID + lane * 4) = acc;
}

// ---------------- gate branch ----------------
__global__ void normalize_alpha_kernel(const float* __restrict__ alpha, int n) {
    int v = blockIdx.x * blockDim.x + threadIdx.x;
    if (v >= n) return;
    const float4* a = (const float4*)(alpha + (size_t)v * PROTO);
    float4 vals[16];
    float ss = 0.f;
#pragma unroll
    for (int i = 0; i < 16; i++) {
        vals[i] = a[i];
        ss += vals[i].x * vals[i].x + vals[i].y * vals[i].y +
              vals[i].z * vals[i].z + vals[i].w * vals[i].w;
    }
    float inv = 1.0f / fmaxf(sqrtf(ss), 1e-12f);
    float4* o = (float4*)(g_an + (size_t)v * PROTO);
#pragma unroll
    for (int i = 0; i < 16; i++) {
        float4 t = vals[i];
        t.x *= inv; t.y *= inv; t.z *= inv; t.w *= inv;
        o[i] = t;
    }
}

__global__ __launch_bounds__(256) void gate_gather_kernel(const float* __restrict__ temp,
                                                          float* __restrict__ out, int n) {
    int lane = threadIdx.x & 31;
    int v = blockIdx.x * 8 + (threadIdx.x >> 5);
    if (v >= n) return;
    int d0 = g_off[v];
    int c = g_cnt[v];
    int d1 = d0 + c;
    float2 acc = make_float2(0.f, 0.f);
    for (int j0 = d0; j0 < d1; j0 += 32) {
        int m = d1 - j0; if (m > 32) m = 32;
        int ul = (j0 + lane < d1) ? g_csr[j0 + lane] : 0;
        int t = 0;
        for (; t + 4 <= m; t += 4) {
            int u0 = __shfl_sync(0xFFFFFFFFu, ul, t);
            int u1 = __shfl_sync(0xFFFFFFFFu, ul, t + 1);
            int u2 = __shfl_sync(0xFFFFFFFFu, ul, t + 2);
            int u3 = __shfl_sync(0xFFFFFFFFu, ul, t + 3);
            float2 x0 = *(const float2*)(g_an + (size_t)u0 * PROTO + lane * 2);
            float2 x1 = *(const float2*)(g_an + (size_t)u1 * PROTO + lane * 2);
            float2 x2 = *(const float2*)(g_an + (size_t)u2 * PROTO + lane * 2);
            float2 x3 = *(const float2*)(g_an + (size_t)u3 * PROTO + lane * 2);
            acc.x += (x0.x + x1.x) + (x2.x + x3.x);
            acc.y += (x0.y + x1.y) + (x2.y + x3.y);
        }
        for (; t < m; t++) {
            int u = __shfl_sync(0xFFFFFFFFu, ul, t);
            float2 x = *(const float2*)(g_an + (size_t)u * PROTO + lane * 2);
            acc.x += x.x; acc.y += x.y;
        }
    }
    float2 av = *(const float2*)(g_an + (size_t)v * PROTO + lane * 2);
    float d = acc.x * av.x + acc.y * av.y;
#pragma unroll
    for (int s = 16; s > 0; s >>= 1) d += __shfl_down_sync(0xFFFFFFFFu, d, s);
    if (lane == 0) {
        float tv = __ldg(temp);
        float m = (1.0f + d) / (float)(c + 1);
        out[v] = 1.0f / (1.0f + expf(-tv * m));
    }
}

// ---------------- 3xTF32 tensor-core GEMM v7: single-matrix, optional ACCUM into C ----------------
#define ASZ6 2304
template<int K, int STATS, int TRS, int TRA, bool ACCUM>
__global__ __launch_bounds__(256, 3) void mma_gemm_kernel(
    const float* __restrict__ A1,
    int w1p,
    const float* __restrict__ bias, float* __restrict__ C, int n)
{
    __shared__ float As[2 * ASZ6];
    __shared__ float ssum[HID], ssq[HID];

    const int tid  = threadIdx.x;
    const int lane = tid & 31;
    const int w    = tid >> 5;
    const int row0 = blockIdx.x * 64;
    const int mt   = (w & 1) * 32;
    const int wn   = w >> 1;
    const int nb   = wn * 32;
    const int t4 = lane & 3;
    const int g4 = lane >> 2;

    if (STATS >= 0 && tid < HID) { ssum[tid] = 0.f; ssq[tid] = 0.f; }

    float acc[2][4][4];
#pragma unroll
    for (int j = 0; j < 4; j++) {
        float b0 = 0.f, b1 = 0.f;
        if (!ACCUM) {
            int c0 = nb + j * 8 + 2 * t4;
            b0 = bias[c0]; b1 = bias[c0 + 1];
        }
#pragma unroll
        for (int m2 = 0; m2 < 2; m2++) {
            acc[m2][j][0] = b0; acc[m2][j][1] = b1; acc[m2][j][2] = b0; acc[m2][j][3] = b1;
        }
    }

    constexpr int TOT = K / KC;

    const int ar0 = tid >> 3;
    const int akq = tid & 7;
    const int ar1 = ar0 + 32;
    const int gr0 = row0 + ar0, gr1 = row0 + ar1;

    auto xform = [&](float4& v, int cb) {
        if (TRS >= 0) {
            float4 sc = *(const float4*)&g_scaleS[TRS][cb];
            float4 sh = *(const float4*)&g_shiftS[TRS][cb];
            v.x = v.x * sc.x + sh.x; v.y = v.y * sc.y + sh.y;
            v.z = v.z * sc.z + sh.z; v.w = v.w * sc.w + sh.w;
            if (TRA == 0) {
                v.x = fmaxf(v.x, 0.f); v.y = fmaxf(v.y, 0.f);
                v.z = fmaxf(v.z, 0.f); v.w = fmaxf(v.w, 0.f);
            } else {
                v.x = 1.f / (1.f + expf(-v.x)); v.y = 1.f / (1.f + expf(-v.y));
                v.z = 1.f / (1.f + expf(-v.z)); v.w = 1.f / (1.f + expf(-v.w));
            }
        }
    };

    auto loadA = [&](int ch, float4& p0, float4& p1) {
        int k0 = ch * KC;
        p0 = (gr0 < n) ? ldg_ef4(A1 + (size_t)gr0 * K + k0 + akq * 4) : make_float4(0, 0, 0, 0);
        p1 = (gr1 < n) ? ldg_ef4(A1 + (size_t)gr1 * K + k0 + akq * 4) : make_float4(0, 0, 0, 0);
        if (gr0 < n) xform(p0, k0 + akq * 4);
        if (gr1 < n) xform(p1, k0 + akq * 4);
    };
    auto storeA = [&](int buf, const float4& p0, const float4& p1) {
        *(float4*)&As[buf * ASZ6 + ar0 * 36 + akq * 4] = p0;
        *(float4*)&As[buf * ASZ6 + ar1 * 36 + akq * 4] = p1;
    };

    {
        float4 p0, p1;
        loadA(0, p0, p1);
        storeA(0, p0, p1);
    }
    __syncthreads();

#pragma unroll 1
    for (int ch = 0; ch < TOT; ch++) {
        const int cur = ch & 1, nxt = cur ^ 1;
        const bool more = (ch + 1 < TOT);
        float4 p0, p1;
        if (more) loadA(ch + 1, p0, p1);
        {
            const float* Ac = As + cur * ASZ6;
            const int wbase = w1p + ch * 2048;
#pragma unroll
            for (int kt = 0; kt < 4; kt++) {
                uint32 ah[2][4], al[2][4];
#pragma unroll
                for (int m2 = 0; m2 < 2; m2++) {
                    int base = (mt + m2 * 16 + g4) * 36 + kt * 8 + t4;
                    float ra0 = Ac[base], ra1 = Ac[base + 8 * 36];
                    float ra2 = Ac[base + 4], ra3 = Ac[base + 8 * 36 + 4];
                    float h0, l0, h1, l1, h2, l2, h3, l3;
                    split_tf32(ra0, h0, l0); split_tf32(ra1, h1, l1);
                    split_tf32(ra2, h2, l2); split_tf32(ra3, h3, l3);
                    ah[m2][0] = __float_as_uint(h0); ah[m2][1] = __float_as_uint(h1);
                    ah[m2][2] = __float_as_uint(h2); ah[m2][3] = __float_as_uint(h3);
                    al[m2][0] = __float_as_uint(l0); al[m2][1] = __float_as_uint(l1);
                    al[m2][2] = __float_as_uint(l2); al[m2][3] = __float_as_uint(l3);
                }
#pragma unroll
                for (int j = 0; j < 4; j++) {
                    int jg = wn * 4 + j;
                    int pidx = wbase + (kt * 16 + jg) * 32 + lane;
                    float4 bf = ldg_el4(g_wf + (size_t)pidx * 4);
                    uint32 bh0 = __float_as_uint(bf.x), bh1 = __float_as_uint(bf.y);
                    uint32 bl0 = __float_as_uint(bf.z), bl1 = __float_as_uint(bf.w);
#pragma unroll
                    for (int m2 = 0; m2 < 2; m2++) {
                        mma_tf32(acc[m2][j], ah[m2][0], ah[m2][1], ah[m2][2], ah[m2][3], bh0, bh1);
                        mma_tf32(acc[m2][j], ah[m2][0], ah[m2][1], ah[m2][2], ah[m2][3], bl0, bl1);
                        mma_tf32(acc[m2][j], al[m2][0], al[m2][1], al[m2][2], al[m2][3], bh0, bh1);
                    }
                }
            }
        }
        if (more) storeA(nxt, p0, p1);
        __syncthreads();
    }

#pragma unroll
    for (int j = 0; j < 4; j++) {
        int c0 = nb + j * 8 + 2 * t4;
        float s0 = 0.f, s1 = 0.f, q0 = 0.f, q1 = 0.f;
#pragma unroll
        for (int m2 = 0; m2 < 2; m2++) {
            int r0 = row0 + mt + m2 * 16 + g4;
            int r1 = r0 + 8;
            if (r0 < n) {
                float v0 = acc[m2][j][0], v1 = acc[m2][j][1];
                if (ACCUM) {
                    float2 pr = *(float2*)(C + (size_t)r0 * HID + c0);
                    v0 += pr.x; v1 += pr.y;
                }
                *(float2*)(C + (size_t)r0 * HID + c0) = make_float2(v0, v1);
                s0 += v0; s1 += v1; q0 += v0 * v0; q1 += v1 * v1;
            }
            if (r1 < n) {
                float v0 = acc[m2][j][2], v1 = acc[m2][j][3];
                if (ACCUM) {
                    float2 pr = *(float2*)(C + (size_t)r1 * HID + c0);
                    v0 += pr.x; v1 += pr.y;
                }
                *(float2*)(C + (size_t)r1 * HID + c0) = make_float2(v0, v1);
                s0 += v0; s1 += v1; q0 += v0 * v0; q1 += v1 * v1;
            }
        }
        if (STATS >= 0) {
            atomicAdd(&ssum[c0], s0); atomicAdd(&ssum[c0 + 1], s1);
            atomicAdd(&ssq[c0], q0);  atomicAdd(&ssq[c0 + 1], q1);
        }
    }
    if (STATS >= 0) {
        __syncthreads();
        if (tid < HID) {
            atomicAdd(&g_sum[STATS * HID + tid], ssum[tid]);
            atomicAdd(&g_sumsq[STATS * HID + tid], ssq[tid]);
        }
    }
}

// ---------------- BN finalize ----------------
__global__ void stats_final_kernel(const float* __restrict__ gamma, const float* __restrict__ beta,
                                   float inv_n, int slot) {
    int c = threadIdx.x;
    float mu = g_sum[slot * HID + c] * inv_n;
    float var = g_sumsq[slot * HID + c] * inv_n - mu * mu;
    float sc = gamma[c] * rsqrtf(var + BN_EPS);
    g_scaleS[slot][c] = sc;
    g_shiftS[slot][c] = beta[c] - mu * sc;
}

// ---------------- classifier + log_softmax ----------------
__global__ __launch_bounds__(256) void classifier_kernel(
    const float* __restrict__ hg, const float* __restrict__ hp,
    const float* __restrict__ Wc, const float* __restrict__ bc,
    float* __restrict__ out, int n)
{
    __shared__ float wcs[40 * 256];
    __shared__ float bcs[40];
    int tid = threadIdx.x;
    for (int i = tid; i < 40 * 256; i += 256) wcs[i] = Wc[i];
    if (tid < 40) bcs[tid] = bc[tid];
    __syncthreads();
    int r = blockIdx.x * 256 + tid;
    if (r >= n) return;

    float acc[40];
#pragma unroll
    for (int o = 0; o < 40; o++) acc[o] = bcs[o];

    for (int half = 0; half < 2; half++) {
        const float* src = half ? hp : hg;
        for (int k4 = 0; k4 < 32; k4++) {
            float4 z = *(const float4*)(src + (size_t)r * HID + k4 * 4);
            z.x = fmaxf(z.x, 0.f); z.y = fmaxf(z.y, 0.f);
            z.z = fmaxf(z.z, 0.f); z.w = fmaxf(z.w, 0.f);
            int kb = half * 128 + k4 * 4;
#pragma unroll
            for (int o = 0; o < 40; o++) {
                float4 wv = *(float4*)&wcs[o * 256 + kb];
                acc[o] += z.x * wv.x + z.y * wv.y + z.z * wv.z + z.w * wv.w;
            }
        }
    }
    float m = acc[0];
#pragma unroll
    for (int o = 1; o < 40; o++) m = fmaxf(m, acc[o]);
    float s = 0.f;
#pragma unroll
    for (int o = 0; o < 40; o++) s += expf(acc[o] - m);
    float lse = m + logf(s);
    float* op = out + (size_t)r * 40;
#pragma unroll
    for (int o = 0; o < 40; o++) op[o] = acc[o] - lse;
}

// ---------------- streams (created at program init; no device allocation) ----------------
struct StreamInit {
    cudaStream_t s1, s2; cudaEvent_t evF, evC, evJ, evS0, evS1, evP0, evP1, evP2; bool ok;
    StreamInit() {
        ok = (cudaStreamCreateWithFlags(&s1, cudaStreamNonBlocking) == cudaSuccess) &&
             (cudaStreamCreateWithFlags(&s2, cudaStreamNonBlocking) == cudaSuccess) &&
             (cudaEventCreateWithFlags(&evF,  cudaEventDisableTiming) == cudaSuccess) &&
             (cudaEventCreateWithFlags(&evC,  cudaEventDisableTiming) == cudaSuccess) &&
             (cudaEventCreateWithFlags(&evJ,  cudaEventDisableTiming) == cudaSuccess) &&
             (cudaEventCreateWithFlags(&evS0, cudaEventDisableTiming) == cudaSuccess) &&
             (cudaEventCreateWithFlags(&evS1, cudaEventDisableTiming) == cudaSuccess) &&
             (cudaEventCreateWithFlags(&evP0, cudaEventDisableTiming) == cudaSuccess) &&
             (cudaEventCreateWithFlags(&evP1, cudaEventDisableTiming) == cudaSuccess) &&
             (cudaEventCreateWithFlags(&evP2, cudaEventDisableTiming) == cudaSuccess);
    }
};
static StreamInit g_si;

// ---------------- launcher ----------------
extern "C" void kernel_launch(void* const* d_in, const int* in_sizes, int n_in,
                              void* d_out, int out_size) {
    const float* x           = (const float*)d_in[0];
    const float* alpha       = (const float*)d_in[1];
    const int*   ei          = (const int*)d_in[2];
    const float* sage_Wl     = (const float*)d_in[3];
    const float* sage_bl     = (const float*)d_in[4];
    const float* sage_Wr     = (const float*)d_in[5];
    const float* sage_bng    = (const float*)d_in[6];
    const float* sage_bnb    = (const float*)d_in[7];
    const float* mlp_W0      = (const float*)d_in[8];
    const float* mlp_b0      = (const float*)d_in[9];
    const float* mlp_W1      = (const float*)d_in[10];
    const float* mlp_b1      = (const float*)d_in[11];
    const float* mlp_W2      = (const float*)d_in[12];
    const float* mlp_b2      = (const float*)d_in[13];
    const float* mlp_bng     = (const float*)d_in[14];
    const float* mlp_bnb     = (const float*)d_in[15];
    const float* W_cls       = (const float*)d_in[16];
    const float* b_cls       = (const float*)d_in[17];
    const float* temperature = (const float*)d_in[18];

    int n = in_sizes[0] / HID;
    int E = in_sizes[2] / 2;
    const int* src = ei;
    const int* tgt = ei + E;
    float* out = (float*)d_out;

    float *h1, *h2, *agg, *p, *p2;
    cudaGetSymbolAddress((void**)&h1,  g_h1);
    cudaGetSymbolAddress((void**)&h2,  g_h2);
    cudaGetSymbolAddress((void**)&agg, g_agg);
    cudaGetSymbolAddress((void**)&p,   g_p);
    cudaGetSymbolAddress((void**)&p2,  g_p2);

    const int TB = 256;
    int nodeBlocks = (n + TB - 1) / TB;
    int warpNodeBlocks = (n + 7) / 8;
    int gemmBlocks = (n + 63) / 64;
    float inv_n = 1.0f / (float)n;
    int eBlocks = (E + TB - 1) / TB;

    bool fork = g_si.ok;
    cudaStream_t sp = fork ? g_si.s1 : (cudaStream_t)0;   // proto + gate
    cudaStream_t ss = fork ? g_si.s2 : (cudaStream_t)0;   // self-GEMMs

    // ---- shared prologue (main stream) ----
    init_kernel<<<2, TB>>>();
    prep_w_kernel<<<(NPAIRS + TB - 1) / TB, TB>>>(sage_Wl, sage_Wr, mlp_W0, mlp_W1, mlp_W2);

    if (fork) {
        cudaEventRecord(g_si.evF, 0);
        cudaStreamWaitEvent(sp, g_si.evF, 0);
        cudaStreamWaitEvent(ss, g_si.evF, 0);
    }

    // ---- proto branch (stream s1) ----
    normalize_alpha_kernel<<<nodeBlocks, TB, 0, sp>>>(alpha, n);
    mma_gemm_kernel<64, 2, -1, 0, false><<<gemmBlocks, TB, 0, sp>>>(alpha, MP0, mlp_b0, p, n);
    stats_final_kernel<<<1, HID, 0, sp>>>(mlp_bng, mlp_bnb, inv_n, 2);
    mma_gemm_kernel<128, 3, 2, 1, false><<<gemmBlocks, TB, 0, sp>>>(p, MP1, mlp_b1, p2, n);
    stats_final_kernel<<<1, HID, 0, sp>>>(mlp_bng + HID, mlp_bnb + HID, inv_n, 3);
    mma_gemm_kernel<128, -1, 3, 1, false><<<gemmBlocks, TB, 0, sp>>>(p2, MP2, mlp_b2, p, n);

    // ---- self GEMM layer 0 (stream s2): h1 = x @ Wr0 + b0 ----
    mma_gemm_kernel<128, -1, -1, 0, false><<<gemmBlocks, TB, 0, ss>>>(x, WPR(0), sage_bl, h1, n);
    if (fork) cudaEventRecord(g_si.evP0, ss);

    // ---- CSR build (main stream, concurrent) ----
    zero_cnt_kernel<<<nodeBlocks, TB>>>(n);
    count_kernel<<<eBlocks, TB>>>(tgt, E);
    alloc_kernel<<<nodeBlocks, TB>>>(n);
    fill_kernel<<<eBlocks, TB>>>(src, tgt, E);
    if (fork) cudaEventRecord(g_si.evC, 0);

    // ---- gate on s1 after proto + CSR ready ----
    if (fork) cudaStreamWaitEvent(sp, g_si.evC, 0);
    gate_gather_kernel<<<warpNodeBlocks, TB, 0, sp>>>(temperature, out + (size_t)n * 40, n);
    if (fork) cudaEventRecord(g_si.evJ, sp);

    // ---- SAGE layer 0 (main): gather(x) || self0; then h1 += agg @ Wl0, stats slot0 ----
    gather_agg_kernel<-1><<<warpNodeBlocks, TB>>>(x, agg, n);
    if (fork) cudaStreamWaitEvent(0, g_si.evP0, 0);
    mma_gemm_kernel<128, 0, -1, 0, true><<<gemmBlocks, TB>>>(agg, WPL(0), sage_bl, h1, n);
    stats_final_kernel<<<1, HID>>>(sage_bng, sage_bnb, inv_n, 0);
    if (fork) cudaEventRecord(g_si.evS0, 0);

    // ---- self GEMM layer 1 (s2): h2 = bn_relu(h1) @ Wr1 + b1 ----
    if (fork) cudaStreamWaitEvent(ss, g_si.evS0, 0);
    mma_gemm_kernel<128, -1, 0, 0, false><<<gemmBlocks, TB, 0, ss>>>(h1, WPR(1), sage_bl + HID, h2, n);
    if (fork) cudaEventRecord(g_si.evP1, ss);

    // ---- SAGE layer 1 (main) ----
    gather_agg_kernel<0><<<warpNodeBlocks, TB>>>(h1, agg, n);
    if (fork) cudaStreamWaitEvent(0, g_si.evP1, 0);
    mma_gemm_kernel<128, 1, -1, 0, true><<<gemmBlocks, TB>>>(agg, WPL(1), sage_bl + HID, h2, n);
    stats_final_kernel<<<1, HID>>>(sage_bng + HID, sage_bnb + HID, inv_n, 1);
    if (fork) cudaEventRecord(g_si.evS1, 0);

    // ---- self GEMM layer 2 (s2): h1 = bn_relu(h2) @ Wr2 + b2 ----
    if (fork) cudaStreamWaitEvent(ss, g_si.evS1, 0);
    mma_gemm_kernel<128, -1, 1, 0, false><<<gemmBlocks, TB, 0, ss>>>(h2, WPR(2), sage_bl + 2 * HID, h1, n);
    if (fork) cudaEventRecord(g_si.evP2, ss);

    // ---- SAGE layer 2 (main) ----
    gather_agg_kernel<1><<<warpNodeBlocks, TB>>>(h2, agg, n);
    if (fork) cudaStreamWaitEvent(0, g_si.evP2, 0);
    mma_gemm_kernel<128, -1, -1, 0, true><<<gemmBlocks, TB>>>(agg, WPL(2), sage_bl + 2 * HID, h1, n);

    // ---- join gate, then fusion + classifier ----
    if (fork) cudaStreamWaitEvent(0, g_si.evJ, 0);
    classifier_kernel<<<nodeBlocks, TB>>>(h1, p, W_cls, b_cls, out, n);
}

// round 17
// speedup vs baseline: 1.1152x; 1.1152x over previous
#include <cuda_runtime.h>
#include <cuda_bf16.h>
#include <math.h>

#define NMAX 100000
#define EMAX 1700000
#define HID 128
#define PROTO 64
#define BN_EPS 1e-5f
#define KC 32

typedef unsigned int uint32;

// ---------------- scratch (device globals: no allocation allowed) ----------------
__device__ float g_h1[NMAX * HID];
__device__ float g_h2[NMAX * HID];
__device__ float g_agg[NMAX * HID];
__device__ float g_p[NMAX * HID];
__device__ float g_p2[NMAX * HID];
__device__ float g_an[NMAX * PROTO];
__device__ int   g_cnt[NMAX];
__device__ int   g_off[NMAX + 1];
__device__ int   g_cur[NMAX];
__device__ int   g_csr[EMAX];
__device__ int   g_total;
__device__ float g_sum[4 * HID];
__device__ float g_sumsq[4 * HID];
__device__ float g_scaleS[4][HID];
__device__ float g_shiftS[4][HID];

// Weights in INTERLEAVED tf32 fragment layout: one float4 per "pair"
#define WPL(L) ((L) * 8192)
#define WPR(L) (24576 + (L) * 8192)
#define MP0 49152
#define MP1 53248
#define MP2 61440
#define NPAIRS 69632
__device__ float g_wf[NPAIRS * 4];

// ---------------- tf32 + cache-hint helpers ----------------
__device__ __forceinline__ uint32 cvt_tf32(float x) {
    uint32 r;
    asm("cvt.rna.tf32.f32 %0, %1;" : "=r"(r) : "f"(x));
    return r;
}
__device__ __forceinline__ void split_tf32(float x, float& hi, float& lo) {
    uint32 h = cvt_tf32(x);
    hi = __uint_as_float(h);
    lo = __uint_as_float(cvt_tf32(x - hi));
}
__device__ __forceinline__ void mma_tf32(float* c,
                                         uint32 a0, uint32 a1, uint32 a2, uint32 a3,
                                         uint32 b0, uint32 b1) {
    asm volatile("mma.sync.aligned.m16n8k8.row.col.f32.tf32.tf32.f32 "
                 "{%0,%1,%2,%3}, {%4,%5,%6,%7}, {%8,%9}, {%0,%1,%2,%3};"
                 : "+f"(c[0]), "+f"(c[1]), "+f"(c[2]), "+f"(c[3])
                 : "r"(a0), "r"(a1), "r"(a2), "r"(a3), "r"(b0), "r"(b1));
}
__device__ __forceinline__ float4 ldg_ef4(const float* p) {
    float4 v;
    asm("ld.global.nc.L1::evict_first.v4.f32 {%0,%1,%2,%3}, [%4];"
        : "=f"(v.x), "=f"(v.y), "=f"(v.z), "=f"(v.w) : "l"(p));
    return v;
}
__device__ __forceinline__ float4 ldg_el4(const float* p) {
    float4 v;
    asm("ld.global.nc.L1::evict_last.v4.f32 {%0,%1,%2,%3}, [%4];"
        : "=f"(v.x), "=f"(v.y), "=f"(v.z), "=f"(v.w) : "l"(p));
    return v;
}
__device__ __forceinline__ float4 ldg_nc4(const float* p) {
    float4 v;
    asm("ld.global.nc.v4.f32 {%0,%1,%2,%3}, [%4];"
        : "=f"(v.x), "=f"(v.y), "=f"(v.z), "=f"(v.w) : "l"(p));
    return v;
}
__device__ __forceinline__ float2 ldg_nc2(const float* p) {
    float2 v;
    asm("ld.global.nc.v2.f32 {%0,%1}, [%2];"
        : "=f"(v.x), "=f"(v.y) : "l"(p));
    return v;
}

// ---------------- init ----------------
__global__ void init_kernel() {
    int v = blockIdx.x * blockDim.x + threadIdx.x;
    if (v < 4 * HID) { g_sum[v] = 0.f; g_sumsq[v] = 0.f; }
    if (v == 0) g_total = 0;
}

__global__ void zero_cnt_kernel(int n) {
    int v = blockIdx.x * blockDim.x + threadIdx.x;
    if (v < n) g_cnt[v] = 0;
}
__global__ void count_kernel(const int* __restrict__ tgt, int E) {
    int e = blockIdx.x * blockDim.x + threadIdx.x;
    if (e < E) atomicAdd(&g_cnt[tgt[e]], 1);
}

// ---------------- CSR offset allocation (unordered block bases) ----------------
__global__ void alloc_kernel(int n) {
    __shared__ int wsums[8];
    __shared__ int base_s;
    int tid = threadIdx.x, lane = tid & 31, wid = tid >> 5;
    int i = blockIdx.x * 256 + tid;
    int v = (i < n) ? g_cnt[i] : 0;
    int s = v;
#pragma unroll
    for (int d = 1; d < 32; d <<= 1) {
        int t = __shfl_up_sync(0xFFFFFFFFu, s, d);
        if (lane >= d) s += t;
    }
    if (lane == 31) wsums[wid] = s;
    __syncthreads();
    if (tid == 0) {
        int run = 0;
#pragma unroll
        for (int w8 = 0; w8 < 8; w8++) { int t = wsums[w8]; wsums[w8] = run; run += t; }
        base_s = atomicAdd(&g_total, run);
    }
    __syncthreads();
    int excl = base_s + wsums[wid] + s - v;
    if (i < n) { g_off[i] = excl; g_cur[i] = excl; }
}

__global__ void fill_kernel(const int* __restrict__ src, const int* __restrict__ tgt, int E) {
    int e = blockIdx.x * blockDim.x + threadIdx.x;
    if (e >= E) return;
    int t = tgt[e];
    int pos = atomicAdd(&g_cur[t], 1);
    g_csr[pos] = src[e];
}

// ---------------- weight prep ----------------
__global__ void prep_w_kernel(const float* __restrict__ sWl, const float* __restrict__ sWr,
                              const float* __restrict__ m0, const float* __restrict__ m1,
                              const float* __restrict__ m2) {
    int i = blockIdx.x * blockDim.x + threadIdx.x;
    if (i >= NPAIRS) return;
    int off, K;
    const float* mat;
    if (i < 24576)        { int L = i / 8192;           off = L * 8192;           mat = sWl + L * 16384; K = 128; }
    else if (i < 49152)   { int L = (i - 24576) / 8192; off = 24576 + L * 8192;   mat = sWr + L * 16384; K = 128; }
    else if (i < 53248)   { off = MP0; mat = m0; K = 64; }
    else if (i < 61440)   { off = MP1; mat = m1; K = 128; }
    else                  { off = MP2; mat = m2; K = 128; }
    int li   = i - off;
    int lane = li & 31;
    int nt   = (li >> 5) & 15;
    int kt   = li >> 9;
    int g4 = lane >> 2, t4 = lane & 3;
    int c = nt * 8 + g4;
    int k = kt * 8 + t4;
    float v0 = mat[c * K + k];
    float v1 = mat[c * K + k + 4];
    float h0, l0, h1, l1;
    split_tf32(v0, h0, l0);
    split_tf32(v1, h1, l1);
    *(float4*)&g_wf[(size_t)i * 4] = make_float4(h0, h1, l0, l1);
}

// ---------------- gather aggregation (segment mean), warp per node, MLP=4 ----------------
template<int SLOT>
__global__ __launch_bounds__(256) void gather_agg_kernel(const float* __restrict__ h,
                                                         float* __restrict__ agg, int n) {
    int lane = threadIdx.x & 31;
    int v = blockIdx.x * 8 + (threadIdx.x >> 5);
    if (v >= n) return;
    int d0 = g_off[v];
    int c = g_cnt[v];
    int d1 = d0 + c;
    float4 sc, sh;
    if (SLOT >= 0) {
        sc = *(const float4*)&g_scaleS[SLOT][lane * 4];
        sh = *(const float4*)&g_shiftS[SLOT][lane * 4];
    }
    float4 acc = make_float4(0.f, 0.f, 0.f, 0.f);
    for (int j0 = d0; j0 < d1; j0 += 32) {
        int m = d1 - j0; if (m > 32) m = 32;
        int ul = (j0 + lane < d1) ? g_csr[j0 + lane] : 0;
        int t = 0;
        for (; t + 4 <= m; t += 4) {
            int u0 = __shfl_sync(0xFFFFFFFFu, ul, t);
            int u1 = __shfl_sync(0xFFFFFFFFu, ul, t + 1);
            int u2 = __shfl_sync(0xFFFFFFFFu, ul, t + 2);
            int u3 = __shfl_sync(0xFFFFFFFFu, ul, t + 3);
            float4 x0 = ldg_nc4(h + (size_t)u0 * HID + lane * 4);
            float4 x1 = ldg_nc4(h + (size_t)u1 * HID + lane * 4);
            float4 x2 = ldg_nc4(h + (size_t)u2 * HID + lane * 4);
            float4 x3 = ldg_nc4(h + (size_t)u3 * HID + lane * 4);
            if (SLOT >= 0) {
                x0.x = fmaxf(x0.x * sc.x + sh.x, 0.f); x0.y = fmaxf(x0.y * sc.y + sh.y, 0.f);
                x0.z = fmaxf(x0.z * sc.z + sh.z, 0.f); x0.w = fmaxf(x0.w * sc.w + sh.w, 0.f);
                x1.x = fmaxf(x1.x * sc.x + sh.x, 0.f); x1.y = fmaxf(x1.y * sc.y + sh.y, 0.f);
                x1.z = fmaxf(x1.z * sc.z + sh.z, 0.f); x1.w = fmaxf(x1.w * sc.w + sh.w, 0.f);
                x2.x = fmaxf(x2.x * sc.x + sh.x, 0.f); x2.y = fmaxf(x2.y * sc.y + sh.y, 0.f);
                x2.z = fmaxf(x2.z * sc.z + sh.z, 0.f); x2.w = fmaxf(x2.w * sc.w + sh.w, 0.f);
                x3.x = fmaxf(x3.x * sc.x + sh.x, 0.f); x3.y = fmaxf(x3.y * sc.y + sh.y, 0.f);
                x3.z = fmaxf(x3.z * sc.z + sh.z, 0.f); x3.w = fmaxf(x3.w * sc.w + sh.w, 0.f);
            }
            acc.x += (x0.x + x1.x) + (x2.x + x3.x);
            acc.y += (x0.y + x1.y) + (x2.y + x3.y);
            acc.z += (x0.z + x1.z) + (x2.z + x3.z);
            acc.w += (x0.w + x1.w) + (x2.w + x3.w);
        }
        for (; t < m; t++) {
            int u = __shfl_sync(0xFFFFFFFFu, ul, t);
            float4 x = ldg_nc4(h + (size_t)u * HID + lane * 4);
            if (SLOT >= 0) {
                x.x = fmaxf(x.x * sc.x + sh.x, 0.f);
                x.y = fmaxf(x.y * sc.y + sh.y, 0.f);
                x.z = fmaxf(x.z * sc.z + sh.z, 0.f);
                x.w = fmaxf(x.w * sc.w + sh.w, 0.f);
            }
            acc.x += x.x; acc.y += x.y; acc.z += x.z; acc.w += x.w;
        }
    }
    float inv = 1.0f / (float)(c > 0 ? c : 1);
    acc.x *= inv; acc.y *= inv; acc.z *= inv; acc.w *= inv;
    *(float4*)(agg + (size_t)v * HID + lane * 4) = acc;
}

// ---------------- gate branch ----------------
__global__ void normalize_alpha_kernel(const float* __restrict__ alpha, int n) {
    int v = blockIdx.x * blockDim.x + threadIdx.x;
    if (v >= n) return;
    const float4* a = (const float4*)(alpha + (size_t)v * PROTO);
    float4 vals[16];
    float ss = 0.f;
#pragma unroll
    for (int i = 0; i < 16; i++) {
        vals[i] = a[i];
        ss += vals[i].x * vals[i].x + vals[i].y * vals[i].y +
              vals[i].z * vals[i].z + vals[i].w * vals[i].w;
    }
    float inv = 1.0f / fmaxf(sqrtf(ss), 1e-12f);
    float4* o = (float4*)(g_an + (size_t)v * PROTO);
#pragma unroll
    for (int i = 0; i < 16; i++) {
        float4 t = vals[i];
        t.x *= inv; t.y *= inv; t.z *= inv; t.w *= inv;
        o[i] = t;
    }
}

__global__ __launch_bounds__(256) void gate_gather_kernel(const float* __restrict__ temp,
                                                          float* __restrict__ out, int n) {
    int lane = threadIdx.x & 31;
    int v = blockIdx.x * 8 + (threadIdx.x >> 5);
    if (v >= n) return;
    int d0 = g_off[v];
    int c = g_cnt[v];
    int d1 = d0 + c;
    float2 acc = make_float2(0.f, 0.f);
    for (int j0 = d0; j0 < d1; j0 += 32) {
        int m = d1 - j0; if (m > 32) m = 32;
        int ul = (j0 + lane < d1) ? g_csr[j0 + lane] : 0;
        int t = 0;
        for (; t + 4 <= m; t += 4) {
            int u0 = __shfl_sync(0xFFFFFFFFu, ul, t);
            int u1 = __shfl_sync(0xFFFFFFFFu, ul, t + 1);
            int u2 = __shfl_sync(0xFFFFFFFFu, ul, t + 2);
            int u3 = __shfl_sync(0xFFFFFFFFu, ul, t + 3);
            float2 x0 = ldg_nc2(g_an + (size_t)u0 * PROTO + lane * 2);
            float2 x1 = ldg_nc2(g_an + (size_t)u1 * PROTO + lane * 2);
            float2 x2 = ldg_nc2(g_an + (size_t)u2 * PROTO + lane * 2);
            float2 x3 = ldg_nc2(g_an + (size_t)u3 * PROTO + lane * 2);
            acc.x += (x0.x + x1.x) + (x2.x + x3.x);
            acc.y += (x0.y + x1.y) + (x2.y + x3.y);
        }
        for (; t < m; t++) {
            int u = __shfl_sync(0xFFFFFFFFu, ul, t);
            float2 x = ldg_nc2(g_an + (size_t)u * PROTO + lane * 2);
            acc.x += x.x; acc.y += x.y;
        }
    }
    float2 av = *(const float2*)(g_an + (size_t)v * PROTO + lane * 2);
    float d = acc.x * av.x + acc.y * av.y;
#pragma unroll
    for (int s = 16; s > 0; s >>= 1) d += __shfl_down_sync(0xFFFFFFFFu, d, s);
    if (lane == 0) {
        float tv = __ldg(temp);
        float m = (1.0f + d) / (float)(c + 1);
        out[v] = 1.0f / (1.0f + expf(-tv * m));
    }
}

// ---------------- 3xTF32 tensor-core GEMM v6 (R14 structure: fused DUAL) ----------------
#define ASZ6 2304
template<int K, bool DUAL, int STATS, int TRS, int TRA>
__global__ __launch_bounds__(256, 3) void mma_gemm_kernel(
    const float* __restrict__ A1, const float* __restrict__ A2,
    int w1p, int w2p,
    const float* __restrict__ bias, float* __restrict__ C, int n)
{
    __shared__ float As[2 * ASZ6];
    __shared__ float ssum[HID], ssq[HID];

    const int tid  = threadIdx.x;
    const int lane = tid & 31;
    const int w    = tid >> 5;
    const int row0 = blockIdx.x * 64;
    const int mt   = (w & 1) * 32;
    const int wn   = w >> 1;
    const int nb   = wn * 32;
    const int t4 = lane & 3;
    const int g4 = lane >> 2;

    if (STATS >= 0 && tid < HID) { ssum[tid] = 0.f; ssq[tid] = 0.f; }

    float acc[2][4][4];
#pragma unroll
    for (int j = 0; j < 4; j++) {
        int c0 = nb + j * 8 + 2 * t4;
        float b0 = bias[c0], b1 = bias[c0 + 1];
#pragma unroll
        for (int m2 = 0; m2 < 2; m2++) {
            acc[m2][j][0] = b0; acc[m2][j][1] = b1; acc[m2][j][2] = b0; acc[m2][j][3] = b1;
        }
    }

    constexpr int NCH = K / KC;
    constexpr int TOT = DUAL ? 2 * NCH : NCH;

    const int ar0 = tid >> 3;
    const int akq = tid & 7;
    const int ar1 = ar0 + 32;
    const int gr0 = row0 + ar0, gr1 = row0 + ar1;

    auto xform = [&](float4& v, int cb) {
        if (TRS >= 0) {
            float4 sc = *(const float4*)&g_scaleS[TRS][cb];
            float4 sh = *(const float4*)&g_shiftS[TRS][cb];
            v.x = v.x * sc.x + sh.x; v.y = v.y * sc.y + sh.y;
            v.z = v.z * sc.z + sh.z; v.w = v.w * sc.w + sh.w;
            if (TRA == 0) {
                v.x = fmaxf(v.x, 0.f); v.y = fmaxf(v.y, 0.f);
                v.z = fmaxf(v.z, 0.f); v.w = fmaxf(v.w, 0.f);
            } else {
                v.x = 1.f / (1.f + expf(-v.x)); v.y = 1.f / (1.f + expf(-v.y));
                v.z = 1.f / (1.f + expf(-v.z)); v.w = 1.f / (1.f + expf(-v.w));
            }
        }
    };

    auto loadA = [&](int ch, float4& p0, float4& p1) {
        bool isA2 = (DUAL && ch >= NCH);
        const float* Ap = isA2 ? A2 : A1;
        int k0 = (ch % NCH) * KC;
        bool tr = DUAL ? isA2 : true;
        p0 = (gr0 < n) ? ldg_ef4(Ap + (size_t)gr0 * K + k0 + akq * 4) : make_float4(0, 0, 0, 0);
        p1 = (gr1 < n) ? ldg_ef4(Ap + (size_t)gr1 * K + k0 + akq * 4) : make_float4(0, 0, 0, 0);
        if (tr) { if (gr0 < n) xform(p0, k0 + akq * 4); if (gr1 < n) xform(p1, k0 + akq * 4); }
    };
    auto storeA = [&](int buf, const float4& p0, const float4& p1) {
        *(float4*)&As[buf * ASZ6 + ar0 * 36 + akq * 4] = p0;
        *(float4*)&As[buf * ASZ6 + ar1 * 36 + akq * 4] = p1;
    };

    {
        float4 p0, p1;
        loadA(0, p0, p1);
        storeA(0, p0, p1);
    }
    __syncthreads();

#pragma unroll 1
    for (int ch = 0; ch < TOT; ch++) {
        const int cur = ch & 1, nxt = cur ^ 1;
        const bool more = (ch + 1 < TOT);
        float4 p0, p1;
        if (more) loadA(ch + 1, p0, p1);
        {
            const float* Ac = As + cur * ASZ6;
            const int wbase = ((DUAL && ch >= NCH) ? w2p : w1p) + (ch % NCH) * 2048;
#pragma unroll
            for (int kt = 0; kt < 4; kt++) {
                uint32 ah[2][4], al[2][4];
#pragma unroll
                for (int m2 = 0; m2 < 2; m2++) {
                    int base = (mt + m2 * 16 + g4) * 36 + kt * 8 + t4;
                    float ra0 = Ac[base], ra1 = Ac[base + 8 * 36];
                    float ra2 = Ac[base + 4], ra3 = Ac[base + 8 * 36 + 4];
                    float h0, l0, h1, l1, h2, l2, h3, l3;
                    split_tf32(ra0, h0, l0); split_tf32(ra1, h1, l1);
                    split_tf32(ra2, h2, l2); split_tf32(ra3, h3, l3);
                    ah[m2][0] = __float_as_uint(h0); ah[m2][1] = __float_as_uint(h1);
                    ah[m2][2] = __float_as_uint(h2); ah[m2][3] = __float_as_uint(h3);
                    al[m2][0] = __float_as_uint(l0); al[m2][1] = __float_as_uint(l1);
                    al[m2][2] = __float_as_uint(l2); al[m2][3] = __float_as_uint(l3);
                }
#pragma unroll
                for (int j = 0; j < 4; j++) {
                    int jg = wn * 4 + j;
                    int pidx = wbase + (kt * 16 + jg) * 32 + lane;
                    float4 bf = ldg_el4(g_wf + (size_t)pidx * 4);
                    uint32 bh0 = __float_as_uint(bf.x), bh1 = __float_as_uint(bf.y);
                    uint32 bl0 = __float_as_uint(bf.z), bl1 = __float_as_uint(bf.w);
#pragma unroll
                    for (int m2 = 0; m2 < 2; m2++) {
                        mma_tf32(acc[m2][j], ah[m2][0], ah[m2][1], ah[m2][2], ah[m2][3], bh0, bh1);
                        mma_tf32(acc[m2][j], ah[m2][0], ah[m2][1], ah[m2][2], ah[m2][3], bl0, bl1);
                        mma_tf32(acc[m2][j], al[m2][0], al[m2][1], al[m2][2], al[m2][3], bh0, bh1);
                    }
                }
            }
        }
        if (more) storeA(nxt, p0, p1);
        __syncthreads();
    }

#pragma unroll
    for (int j = 0; j < 4; j++) {
        int c0 = nb + j * 8 + 2 * t4;
        float s0 = 0.f, s1 = 0.f, q0 = 0.f, q1 = 0.f;
#pragma unroll
        for (int m2 = 0; m2 < 2; m2++) {
            int r0 = row0 + mt + m2 * 16 + g4;
            int r1 = r0 + 8;
            if (r0 < n) {
                *(float2*)(C + (size_t)r0 * HID + c0) = make_float2(acc[m2][j][0], acc[m2][j][1]);
                s0 += acc[m2][j][0]; s1 += acc[m2][j][1];
                q0 += acc[m2][j][0] * acc[m2][j][0]; q1 += acc[m2][j][1] * acc[m2][j][1];
            }
            if (r1 < n) {
                *(float2*)(C + (size_t)r1 * HID + c0) = make_float2(acc[m2][j][2], acc[m2][j][3]);
                s0 += acc[m2][j][2]; s1 += acc[m2][j][3];
                q0 += acc[m2][j][2] * acc[m2][j][2]; q1 += acc[m2][j][3] * acc[m2][j][3];
            }
        }
        if (STATS >= 0) {
            atomicAdd(&ssum[c0], s0); atomicAdd(&ssum[c0 + 1], s1);
            atomicAdd(&ssq[c0], q0);  atomicAdd(&ssq[c0 + 1], q1);
        }
    }
    if (STATS >= 0) {
        __syncthreads();
        if (tid < HID) {
            atomicAdd(&g_sum[STATS * HID + tid], ssum[tid]);
            atomicAdd(&g_sumsq[STATS * HID + tid], ssq[tid]);
        }
    }
}

// ---------------- BN finalize ----------------
__global__ void stats_final_kernel(const float* __restrict__ gamma, const float* __restrict__ beta,
                                   float inv_n, int slot) {
    int c = threadIdx.x;
    float mu = g_sum[slot * HID + c] * inv_n;
    float var = g_sumsq[slot * HID + c] * inv_n - mu * mu;
    float sc = gamma[c] * rsqrtf(var + BN_EPS);
    g_scaleS[slot][c] = sc;
    g_shiftS[slot][c] = beta[c] - mu * sc;
}

// ---------------- classifier + log_softmax ----------------
__global__ __launch_bounds__(256) void classifier_kernel(
    const float* __restrict__ hg, const float* __restrict__ hp,
    const float* __restrict__ Wc, const float* __restrict__ bc,
    float* __restrict__ out, int n)
{
    __shared__ float wcs[40 * 256];
    __shared__ float bcs[40];
    int tid = threadIdx.x;
    for (int i = tid; i < 40 * 256; i += 256) wcs[i] = Wc[i];
    if (tid < 40) bcs[tid] = bc[tid];
    __syncthreads();
    int r = blockIdx.x * 256 + tid;
    if (r >= n) return;

    float acc[40];
#pragma unroll
    for (int o = 0; o < 40; o++) acc[o] = bcs[o];

    for (int half = 0; half < 2; half++) {
        const float* src = half ? hp : hg;
        for (int k4 = 0; k4 < 32; k4++) {
            float4 z = *(const float4*)(src + (size_t)r * HID + k4 * 4);
            z.x = fmaxf(z.x, 0.f); z.y = fmaxf(z.y, 0.f);
            z.z = fmaxf(z.z, 0.f); z.w = fmaxf(z.w, 0.f);
            int kb = half * 128 + k4 * 4;
#pragma unroll
            for (int o = 0; o < 40; o++) {
                float4 wv = *(float4*)&wcs[o * 256 + kb];
                acc[o] += z.x * wv.x + z.y * wv.y + z.z * wv.z + z.w * wv.w;
            }
        }
    }
    float m = acc[0];
#pragma unroll
    for (int o = 1; o < 40; o++) m = fmaxf(m, acc[o]);
    float s = 0.f;
#pragma unroll
    for (int o = 0; o < 40; o++) s += expf(acc[o] - m);
    float lse = m + logf(s);
    float* op = out + (size_t)r * 40;
#pragma unroll
    for (int o = 0; o < 40; o++) op[o] = acc[o] - lse;
}

// ---------------- streams (created at program init; no device allocation) ----------------
struct StreamInit {
    cudaStream_t s1; cudaEvent_t evF, evC, evJ; bool ok;
    StreamInit() {
        ok = (cudaStreamCreateWithFlags(&s1, cudaStreamNonBlocking) == cudaSuccess) &&
             (cudaEventCreateWithFlags(&evF, cudaEventDisableTiming) == cudaSuccess) &&
             (cudaEventCreateWithFlags(&evC, cudaEventDisableTiming) == cudaSuccess) &&
             (cudaEventCreateWithFlags(&evJ, cudaEventDisableTiming) == cudaSuccess);
    }
};
static StreamInit g_si;

// ---------------- launcher ----------------
extern "C" void kernel_launch(void* const* d_in, const int* in_sizes, int n_in,
                              void* d_out, int out_size) {
    const float* x           = (const float*)d_in[0];
    const float* alpha       = (const float*)d_in[1];
    const int*   ei          = (const int*)d_in[2];
    const float* sage_Wl     = (const float*)d_in[3];
    const float* sage_bl     = (const float*)d_in[4];
    const float* sage_Wr     = (const float*)d_in[5];
    const float* sage_bng    = (const float*)d_in[6];
    const float* sage_bnb    = (const float*)d_in[7];
    const float* mlp_W0      = (const float*)d_in[8];
    const float* mlp_b0      = (const float*)d_in[9];
    const float* mlp_W1      = (const float*)d_in[10];
    const float* mlp_b1      = (const float*)d_in[11];
    const float* mlp_W2      = (const float*)d_in[12];
    const float* mlp_b2      = (const float*)d_in[13];
    const float* mlp_bng     = (const float*)d_in[14];
    const float* mlp_bnb     = (const float*)d_in[15];
    const float* W_cls       = (const float*)d_in[16];
    const float* b_cls       = (const float*)d_in[17];
    const float* temperature = (const float*)d_in[18];

    int n = in_sizes[0] / HID;
    int E = in_sizes[2] / 2;
    const int* src = ei;
    const int* tgt = ei + E;
    float* out = (float*)d_out;

    float *h1, *h2, *agg, *p, *p2;
    cudaGetSymbolAddress((void**)&h1,  g_h1);
    cudaGetSymbolAddress((void**)&h2,  g_h2);
    cudaGetSymbolAddress((void**)&agg, g_agg);
    cudaGetSymbolAddress((void**)&p,   g_p);
    cudaGetSymbolAddress((void**)&p2,  g_p2);

    const int TB = 256;
    int nodeBlocks = (n + TB - 1) / TB;
    int warpNodeBlocks = (n + 7) / 8;
    int gemmBlocks = (n + 63) / 64;
    float inv_n = 1.0f / (float)n;
    int eBlocks = (E + TB - 1) / TB;

    bool fork = g_si.ok;
    cudaStream_t sp = fork ? g_si.s1 : (cudaStream_t)0;

    // ---- shared prologue (main stream) ----
    init_kernel<<<2, TB>>>();
    prep_w_kernel<<<(NPAIRS + TB - 1) / TB, TB>>>(sage_Wl, sage_Wr, mlp_W0, mlp_W1, mlp_W2);

    if (fork) {
        cudaEventRecord(g_si.evF, 0);
        cudaStreamWaitEvent(sp, g_si.evF, 0);
    }

    // ---- proto branch (side stream) ----
    normalize_alpha_kernel<<<nodeBlocks, TB, 0, sp>>>(alpha, n);
    mma_gemm_kernel<64, false, 2, -1, 0><<<gemmBlocks, TB, 0, sp>>>(alpha, nullptr, MP0, 0, mlp_b0, p, n);
    stats_final_kernel<<<1, HID, 0, sp>>>(mlp_bng, mlp_bnb, inv_n, 2);
    mma_gemm_kernel<128, false, 3, 2, 1><<<gemmBlocks, TB, 0, sp>>>(p, nullptr, MP1, 0, mlp_b1, p2, n);
    stats_final_kernel<<<1, HID, 0, sp>>>(mlp_bng + HID, mlp_bnb + HID, inv_n, 3);
    mma_gemm_kernel<128, false, -1, 3, 1><<<gemmBlocks, TB, 0, sp>>>(p2, nullptr, MP2, 0, mlp_b2, p, n);

    // ---- CSR build (main stream, concurrent with proto) ----
    zero_cnt_kernel<<<nodeBlocks, TB>>>(n);
    count_kernel<<<eBlocks, TB>>>(tgt, E);
    alloc_kernel<<<nodeBlocks, TB>>>(n);
    fill_kernel<<<eBlocks, TB>>>(src, tgt, E);
    if (fork) cudaEventRecord(g_si.evC, 0);

    // ---- gate on side stream after proto + CSR ready ----
    if (fork) cudaStreamWaitEvent(sp, g_si.evC, 0);
    gate_gather_kernel<<<warpNodeBlocks, TB, 0, sp>>>(temperature, out + (size_t)n * 40, n);
    if (fork) cudaEventRecord(g_si.evJ, sp);

    // ---- SAGE chain (main stream) ----
    gather_agg_kernel<-1><<<warpNodeBlocks, TB>>>(x, agg, n);
    mma_gemm_kernel<128, true, 0, -1, 0><<<gemmBlocks, TB>>>(agg, x, WPL(0), WPR(0), sage_bl, h1, n);
    stats_final_kernel<<<1, HID>>>(sage_bng, sage_bnb, inv_n, 0);

    gather_agg_kernel<0><<<warpNodeBlocks, TB>>>(h1, agg, n);
    mma_gemm_kernel<128, true, 1, 0, 0><<<gemmBlocks, TB>>>(agg, h1, WPL(1), WPR(1), sage_bl + HID, h2, n);
    stats_final_kernel<<<1, HID>>>(sage_bng + HID, sage_bnb + HID, inv_n, 1);

    gather_agg_kernel<1><<<warpNodeBlocks, TB>>>(h2, agg, n);
    mma_gemm_kernel<128, true, -1, 1, 0><<<gemmBlocks, TB>>>(agg, h2, WPL(2), WPR(2), sage_bl + 2 * HID, h1, n);

    // ---- join, then fusion + classifier ----
    if (fork) cudaStreamWaitEvent(0, g_si.evJ, 0);
    classifier_kernel<<<nodeBlocks, TB>>>(h1, p, W_cls, b_cls, out, n);
}